// round 15
// baseline (speedup 1.0000x reference)
#include <cuda_runtime.h>
#include <cstddef>

typedef unsigned long long u64;

// Problem constants
#define B_   8192
#define T_   2048
#define H_   51
#define HP   52            // padded hidden
#define GP   208           // 4*HP padded gate columns
#define BB   64            // batch rows per block
#define BH   32            // batch rows per half
#define NTH  256           // threads per block (two 128-thread halves)
#define NBLK (B_ / BB)     // 128 blocks

#define GPITCH 66          // gsm pair-row pitch (floats): 33 u64 -> conflict-free STS.64
#define NPAIR  (GP / 2)    // 104 column pairs

// Shared memory layout (float offsets)
#define OFF_W1   0                          // [HP][GP]    h1 -> gates1 (k-major)
#define OFF_W2   (OFF_W1 + HP * GP)         // [2*HP][GP]  [h1;h2] -> gates2
#define OFF_WX   (OFF_W2 + 2 * HP * GP)     // [GP]
#define OFF_BS1  (OFF_WX + GP)              // [GP]
#define OFF_BS2  (OFF_BS1 + GP)             // [GP]
#define OFF_WLIN (OFF_BS2 + GP)             // [64]
#define OFF_XS   (OFF_WLIN + 64)            // [64]  (32 per half)
#define OFF_HCAT (OFF_XS + 64)              // per half: [2*HP][BH]
#define HCAT_HALF (2 * HP * BH)
#define OFF_GSM  (OFF_HCAT + 2 * HCAT_HALF) // per half: [NPAIR][GPITCH]
#define GSM_HALF (NPAIR * GPITCH)
#define SMEM_FLOATS (OFF_GSM + 2 * GSM_HALF)
#define SMEM_BYTES  (SMEM_FLOATS * (int)sizeof(float))   // ~214.4 KB

__device__ __forceinline__ float sigf(float v) {
    return __fdividef(1.0f, 1.0f + __expf(-v));
}
__device__ __forceinline__ float tanhfast(float v) {
    return __fdividef(2.0f, 1.0f + __expf(-2.0f * v)) - 1.0f;
}

__device__ __forceinline__ u64 pack2(float lo, float hi) {
    u64 r; asm("mov.b64 %0, {%1, %2};" : "=l"(r) : "f"(lo), "f"(hi)); return r;
}
__device__ __forceinline__ u64 fma2(u64 a, u64 b, u64 c) {
    u64 d; asm("fma.rn.f32x2 %0, %1, %2, %3;" : "=l"(d) : "l"(a), "l"(b), "l"(c)); return d;
}
__device__ __forceinline__ u64 add2(u64 a, u64 b) {
    u64 d; asm("add.rn.f32x2 %0, %1, %2;" : "=l"(d) : "l"(a), "l"(b)); return d;
}

__device__ __forceinline__ void half_bar(int half) {
    asm volatile("bar.sync %0, 128;" :: "r"(half + 1) : "memory");
}

// Register-tiled packed GEMM over one half:
// acc{A,B}[13] (f32x2 over col pairs) += hcat(K x 32) * W(K x 208)
// Thread tile: batch rows (b0, b0+1), cols j0..j0+25 as 13 pairs.
template <int K>
__device__ __forceinline__ void gemm_tile2(const float* __restrict__ W,
                                           const float* __restrict__ hc,
                                           int b0, int j0,
                                           u64 accA[13], u64 accB[13]) {
#pragma unroll
    for (int c = 0; c < 13; c++) { accA[c] = 0ull; accB[c] = 0ull; }
#pragma unroll 4
    for (int k = 0; k < K; k++) {
        float2 hv = *reinterpret_cast<const float2*>(hc + k * BH + b0);
        u64 ha = pack2(hv.x, hv.x);
        u64 hb = pack2(hv.y, hv.y);
        const u64* wr = reinterpret_cast<const u64*>(W + k * GP + j0);
#pragma unroll
        for (int c = 0; c < 13; c++) {
            u64 w = wr[c];
            accA[c] = fma2(ha, w, accA[c]);
            accB[c] = fma2(hb, w, accB[c]);
        }
    }
}

extern __shared__ float smf[];

__global__ __launch_bounds__(NTH, 1)
void lstm_rnn_kernel(const float* __restrict__ x,
                     const float* __restrict__ Wih1, const float* __restrict__ Whh1,
                     const float* __restrict__ bih1, const float* __restrict__ bhh1,
                     const float* __restrict__ Wih2, const float* __restrict__ Whh2,
                     const float* __restrict__ bih2, const float* __restrict__ bhh2,
                     const float* __restrict__ Wlin, const float* __restrict__ blin_p,
                     float* __restrict__ out) {
    float* W1   = smf + OFF_W1;
    float* W2   = smf + OFF_W2;
    float* wx   = smf + OFF_WX;
    float* bs1  = smf + OFF_BS1;
    float* bs2  = smf + OFF_BS2;
    float* wlin = smf + OFF_WLIN;

    const int t    = threadIdx.x;
    const int half = t >> 7;          // 0 or 1
    const int tl   = t & 127;         // lane within half
    const int bbase = blockIdx.x * BB + half * BH;

    float* xs   = smf + OFF_XS   + half * BH;
    float* hcat = smf + OFF_HCAT + half * HCAT_HALF;
    float* gsm  = smf + OFF_GSM  + half * GSM_HALF;

    // ---- one-time init: transpose + pad weights into SMEM (all 256 threads) ----
    for (int idx = t; idx < HP * GP; idx += NTH) {
        int k = idx / GP, gp = idx % GP;
        int g = gp / HP, j = gp % HP;
        W1[idx] = (j < H_ && k < H_) ? Whh1[(g * H_ + j) * H_ + k] : 0.f;
    }
    for (int idx = t; idx < 2 * HP * GP; idx += NTH) {
        int k = idx / GP, gp = idx % GP;
        int g = gp / HP, j = gp % HP;
        float v = 0.f;
        if (j < H_) {
            if (k < H_)                      v = Wih2[(g * H_ + j) * H_ + k];
            else if (k >= HP && k < HP + H_) v = Whh2[(g * H_ + j) * H_ + (k - HP)];
        }
        W2[idx] = v;
    }
    for (int gp = t; gp < GP; gp += NTH) {
        int g = gp / HP, j = gp % HP;
        if (j < H_) {
            wx[gp]  = Wih1[g * H_ + j];
            bs1[gp] = bih1[g * H_ + j] + bhh1[g * H_ + j];
            bs2[gp] = bih2[g * H_ + j] + bhh2[g * H_ + j];
        } else {
            wx[gp] = 0.f; bs1[gp] = 0.f; bs2[gp] = 0.f;
        }
    }
    if (t < 64) wlin[t] = (t < H_) ? Wlin[t] : 0.f;
    for (int idx = t; idx < 2 * HCAT_HALF; idx += NTH) (smf + OFF_HCAT)[idx] = 0.f;
    const float blin = blin_p[0];

    // GEMM tile coordinates (per half)
    const int bg = tl >> 3;            // 0..15
    const int b0 = bg * 2;             // batch rows b0, b0+1
    const int j0 = (tl & 7) * 26;      // 13 col pairs starting at j0 (even)
    const int p0 = j0 >> 1;

    // Elementwise coordinates (per half): thread owns batch row `be`, j = jb + 4i
    const int be = tl & 31;
    const int jb = tl >> 5;            // 0..3

    float c1r[13], c2r[13];
#pragma unroll
    for (int i = 0; i < 13; i++) { c1r[i] = 0.f; c2r[i] = 0.f; }

    float xnext = (tl < BH) ? x[(size_t)(bbase + tl) * T_] : 0.f;

    __syncthreads();

    for (int step = 0; step < T_; ++step) {
        if (tl < BH) xs[tl] = xnext;
        half_bar(half);
        if (tl < BH && step + 1 < T_)
            xnext = __ldg(&x[(size_t)(bbase + tl) * T_ + step + 1]);

        // ---- layer-1 GEMM: gates1 = h1 @ Whh1^T (+ x*wx + bias) ----
        {
            u64 accA[13], accB[13];
            gemm_tile2<HP>(W1, hcat, b0, j0, accA, accB);
            u64 xA = pack2(xs[b0], xs[b0]);
            u64 xB = pack2(xs[b0 + 1], xs[b0 + 1]);
#pragma unroll
            for (int c = 0; c < 13; c++) {
                int gp = j0 + 2 * c;
                u64 bp  = *reinterpret_cast<const u64*>(bs1 + gp);
                u64 wxp = *reinterpret_cast<const u64*>(wx + gp);
                u64 vA = fma2(xA, wxp, add2(accA[c], bp));
                u64 vB = fma2(xB, wxp, add2(accB[c], bp));
                float* row = gsm + (p0 + c) * GPITCH;
                *reinterpret_cast<u64*>(row + b0 * 2)       = vA;
                *reinterpret_cast<u64*>(row + (b0 + 1) * 2) = vB;
            }
        }
        half_bar(half);

        // ---- layer-1 elementwise (h1 -> hcat rows 0..51) ----
#pragma unroll
        for (int i = 0; i < 13; i++) {
            int j = jb + 4 * i;
            int g0 = (0 * HP + j), g1 = (1 * HP + j), g2 = (2 * HP + j), g3 = (3 * HP + j);
            float ig = gsm[(g0 >> 1) * GPITCH + be * 2 + (g0 & 1)];
            float fg = gsm[(g1 >> 1) * GPITCH + be * 2 + (g1 & 1)];
            float gg = gsm[(g2 >> 1) * GPITCH + be * 2 + (g2 & 1)];
            float og = gsm[(g3 >> 1) * GPITCH + be * 2 + (g3 & 1)];
            float ia = sigf(ig), fa = sigf(fg), ga = tanhfast(gg), oa = sigf(og);
            float c = fmaf(fa, c1r[i], ia * ga);
            c1r[i] = c;
            hcat[j * BH + be] = oa * tanhfast(c);
        }
        half_bar(half);

        // ---- layer-2 GEMM: gates2 = [h1;h2] @ [Wih2;Whh2]^T (+ bias) ----
        {
            u64 accA[13], accB[13];
            gemm_tile2<2 * HP>(W2, hcat, b0, j0, accA, accB);
#pragma unroll
            for (int c = 0; c < 13; c++) {
                int gp = j0 + 2 * c;
                u64 bp = *reinterpret_cast<const u64*>(bs2 + gp);
                float* row = gsm + (p0 + c) * GPITCH;
                *reinterpret_cast<u64*>(row + b0 * 2)       = add2(accA[c], bp);
                *reinterpret_cast<u64*>(row + (b0 + 1) * 2) = add2(accB[c], bp);
            }
        }
        half_bar(half);

        // ---- layer-2 elementwise (h2 -> hcat rows 52..103) ----
#pragma unroll
        for (int i = 0; i < 13; i++) {
            int j = jb + 4 * i;
            int g0 = (0 * HP + j), g1 = (1 * HP + j), g2 = (2 * HP + j), g3 = (3 * HP + j);
            float ig = gsm[(g0 >> 1) * GPITCH + be * 2 + (g0 & 1)];
            float fg = gsm[(g1 >> 1) * GPITCH + be * 2 + (g1 & 1)];
            float gg = gsm[(g2 >> 1) * GPITCH + be * 2 + (g2 & 1)];
            float og = gsm[(g3 >> 1) * GPITCH + be * 2 + (g3 & 1)];
            float ia = sigf(ig), fa = sigf(fg), ga = tanhfast(gg), oa = sigf(og);
            float c = fmaf(fa, c2r[i], ia * ga);
            c2r[i] = c;
            hcat[(HP + j) * BH + be] = oa * tanhfast(c);
        }
        half_bar(half);

        // ---- output projection: y[b] = h2 . Wlin + blin ----
        if (tl < BH) {
            float y = blin;
#pragma unroll
            for (int j = 0; j < H_; j++)
                y = fmaf(hcat[(HP + j) * BH + tl], wlin[j], y);
            out[(size_t)(bbase + tl) * T_ + step] = y;
        }
        // loop-top half_bar separates out-proj hcat reads from next write phases
    }
}

extern "C" void kernel_launch(void* const* d_in, const int* in_sizes, int n_in,
                              void* d_out, int out_size) {
    (void)in_sizes; (void)n_in; (void)out_size;
    const float* x    = (const float*)d_in[0];
    const float* Wih1 = (const float*)d_in[1];
    const float* Whh1 = (const float*)d_in[2];
    const float* bih1 = (const float*)d_in[3];
    const float* bhh1 = (const float*)d_in[4];
    const float* Wih2 = (const float*)d_in[5];
    const float* Whh2 = (const float*)d_in[6];
    const float* bih2 = (const float*)d_in[7];
    const float* bhh2 = (const float*)d_in[8];
    const float* Wlin = (const float*)d_in[9];
    const float* blin = (const float*)d_in[10];
    float* out = (float*)d_out;

    cudaFuncSetAttribute(lstm_rnn_kernel,
                         cudaFuncAttributeMaxDynamicSharedMemorySize, SMEM_BYTES);

    lstm_rnn_kernel<<<NBLK, NTH, SMEM_BYTES>>>(x, Wih1, Whh1, bih1, bhh1,
                                               Wih2, Whh2, bih2, bhh2,
                                               Wlin, blin, out);
}

// round 17
// speedup vs baseline: 4.8056x; 4.8056x over previous
#include <cuda_runtime.h>
#include <cuda_bf16.h>
#include <cstdint>
#include <cstddef>

#define B_    8192
#define T_    2048
#define H_    51
#define MR    64            // batch rows per CTA
#define NCTA  (B_ / MR)     // 128
#define NTH   256
#define NT    13            // n8 tiles per warp (N=104 slice)

#define SA    272           // A row stride (bf16); 544B ≡ 32 mod 128 -> conflict-free
#define SB1   80            // B1 row stride; 160B ≡ 32 mod 128
#define SB2   144           // B2 row stride; 288B ≡ 32 mod 128
#define K1S   4             // layer-1 k16 steps (K=64)
#define K2S   7             // layer-2 k16 steps (K=112)

// SMEM byte offsets
#define OFF_A    0                           // [64][SA] bf16: cols 0..127 hi, 128..255 lo
#define A_SZ     (MR * SA * 2)               // 34816
#define OFF_B1H  (OFF_A + A_SZ)
#define B1_SZ    (208 * SB1 * 2)             // 33280
#define OFF_B1L  (OFF_B1H + B1_SZ)
#define OFF_B2H  (OFF_B1L + B1_SZ)
#define B2_SZ    (208 * SB2 * 2)             // 59904
#define OFF_B2L  (OFF_B2H + B2_SZ)
#define OFF_WLIN (OFF_B2L + B2_SZ)           // 52 floats
#define OFF_YSM  (OFF_WLIN + 52 * 4)         // 64 floats
#define SMEM_BYTES (OFF_YSM + 64 * 4)        // ~221.9 KB

// k-permutation within each 16-col block so a v2.u32 load yields (k0,k0+1,k0+8,k0+9)
__device__ __forceinline__ int pcol(int k) {
    int r = k & 15;
    return (k & ~15) + (((r & 7) >> 1) << 2) + ((r >> 3) << 1) + (r & 1);
}

__device__ __forceinline__ float sigf(float v) {
    return __fdividef(1.0f, 1.0f + __expf(-v));
}
__device__ __forceinline__ float tanhfast(float v) {
    return __fdividef(2.0f, 1.0f + __expf(-2.0f * v)) - 1.0f;
}
__device__ __forceinline__ void bsplit(float v, uint16_t& hi, uint16_t& lo) {
    __nv_bfloat16 h = __float2bfloat16(v);
    __nv_bfloat16 l = __float2bfloat16(v - __bfloat162float(h));
    hi = __bfloat16_as_ushort(h);
    lo = __bfloat16_as_ushort(l);
}

__device__ __forceinline__ void mma16816(float d[4], uint32_t a0, uint32_t a1,
                                          uint32_t a2, uint32_t a3,
                                          uint32_t b0, uint32_t b1) {
    asm volatile(
        "mma.sync.aligned.m16n8k16.row.col.f32.bf16.bf16.f32 "
        "{%0,%1,%2,%3}, {%4,%5,%6,%7}, {%8,%9}, {%0,%1,%2,%3};"
        : "+f"(d[0]), "+f"(d[1]), "+f"(d[2]), "+f"(d[3])
        : "r"(a0), "r"(a1), "r"(a2), "r"(a3), "r"(b0), "r"(b1));
}

extern __shared__ char smc[];

__global__ __launch_bounds__(NTH, 1)
void lstm_hmma_kernel(const float* __restrict__ x,
                      const float* __restrict__ Wih1, const float* __restrict__ Whh1,
                      const float* __restrict__ bih1, const float* __restrict__ bhh1,
                      const float* __restrict__ Wih2, const float* __restrict__ Whh2,
                      const float* __restrict__ bih2, const float* __restrict__ bhh2,
                      const float* __restrict__ Wlin, const float* __restrict__ blin_p,
                      float* __restrict__ out) {
    const int tid  = threadIdx.x;
    const int wid  = tid >> 5, lane = tid & 31;
    const int wm   = wid & 3;              // M warp row (16 rows each)
    const int wn   = wid >> 2;             // N warp col (104 cols = 26 units each)
    const int q    = lane & 3;
    const int rql  = lane >> 2;            // 0..7
    const int rowlo = wm * 16 + rql;       // frag rows rowlo, rowlo+8
    const int row_e = rowlo + ((q & 1) ? 8 : 0);   // EW-owned row
    const int bbase = blockIdx.x * MR;

    float* wlinf = (float*)(smc + OFF_WLIN);
    float* ysm   = (float*)(smc + OFF_YSM);

    // ---- one-time init: B tiles (hi/lo, k-permuted), A zero, wlin ----
    // B1[n=4u+g][k]: k<51 Whh1 ; k==52 Wih1(x coef) ; k==53 bias1 ; else 0 ; u==51 dummy->0
    for (int idx = tid; idx < 208 * 64; idx += NTH) {
        int n = idx >> 6, k = idx & 63;
        int u = n >> 2, g = n & 3;
        float v = 0.f;
        if (u < H_) {
            if (k < H_)       v = Whh1[(g * H_ + u) * H_ + k];
            else if (k == 52) v = Wih1[g * H_ + u];
            else if (k == 53) v = bih1[g * H_ + u] + bhh1[g * H_ + u];
        }
        uint16_t hi, lo; bsplit(v, hi, lo);
        int off = (n * SB1 + pcol(k)) * 2;
        *(uint16_t*)(smc + OFF_B1H + off) = hi;
        *(uint16_t*)(smc + OFF_B1L + off) = lo;
    }
    // B2[n][k]: k<51 Wih2 (input = h1) ; k==53 bias2 ; 56<=k<107 Whh2 ; else 0
    for (int idx = tid; idx < 208 * 112; idx += NTH) {
        int n = idx / 112, k = idx - n * 112;
        int u = n >> 2, g = n & 3;
        float v = 0.f;
        if (u < H_) {
            if (k < H_)                      v = Wih2[(g * H_ + u) * H_ + k];
            else if (k == 53)                v = bih2[g * H_ + u] + bhh2[g * H_ + u];
            else if (k >= 56 && k < 56 + H_) v = Whh2[(g * H_ + u) * H_ + (k - 56)];
        }
        uint16_t hi, lo; bsplit(v, hi, lo);
        int off = (n * SB2 + pcol(k)) * 2;
        *(uint16_t*)(smc + OFF_B2H + off) = hi;
        *(uint16_t*)(smc + OFF_B2L + off) = lo;
    }
    for (int i = tid * 16; i < A_SZ; i += NTH * 16)
        *(uint4*)(smc + OFF_A + i) = make_uint4(0u, 0u, 0u, 0u);
    if (tid < 52) wlinf[tid] = (tid < H_) ? Wlin[tid] : 0.f;
    const float blin = blin_p[0];
    __syncthreads();

    // constant-1 col (53) and x(0) col (52); h cols are already zero
    float xnext = 0.f;
    if (tid < MR) {
        uint32_t ab = OFF_A + tid * (SA * 2);
        *(uint16_t*)(smc + ab + pcol(53) * 2) = __bfloat16_as_ushort(__float2bfloat16(1.0f));
        float x0 = x[(size_t)(bbase + tid) * T_];
        uint16_t hi, lo; bsplit(x0, hi, lo);
        *(uint16_t*)(smc + ab + pcol(52) * 2) = hi;
        *(uint16_t*)(smc + ab + (128 + pcol(52)) * 2) = lo;
        xnext = x[(size_t)(bbase + tid) * T_ + 1];
    }
    __syncthreads();

    float d[NT][4];
    float c1[NT], c2[NT];
#pragma unroll
    for (int j = 0; j < NT; j++) { c1[j] = 0.f; c2[j] = 0.f; }

    const uint32_t aq = (uint32_t)(q * 4) * 2;        // byte offset of quad's k-pack
    const uint32_t arow0 = OFF_A + rowlo * (SA * 2);
    const uint32_t arow8 = arow0 + 8 * (SA * 2);

#pragma unroll 1
    for (int step = 0; step < T_; ++step) {
        // ---------------- layer-1 MMA: gates1 (bias & x folded) ----------------
#pragma unroll
        for (int j = 0; j < NT; j++) { d[j][0] = 0.f; d[j][1] = 0.f; d[j][2] = 0.f; d[j][3] = 0.f; }
#pragma unroll
        for (int ks = 0; ks < K1S; ks++) {
            uint32_t ko = (uint32_t)(ks * 16) * 2 + aq;
            uint2 ah01 = *(const uint2*)(smc + arow0 + ko);        // (a0,a2) hi
            uint2 ah13 = *(const uint2*)(smc + arow8 + ko);        // (a1,a3) hi
            uint2 al01 = *(const uint2*)(smc + arow0 + ko + 256);  // lo (+128 cols)
            uint2 al13 = *(const uint2*)(smc + arow8 + ko + 256);
#pragma unroll
            for (int j = 0; j < NT; j++) {
                uint32_t nrow = (uint32_t)(wn * 104 + 8 * j + rql);
                uint32_t bo = nrow * (SB1 * 2) + ko;
                uint2 bh = *(const uint2*)(smc + OFF_B1H + bo);
                uint2 bl = *(const uint2*)(smc + OFF_B1L + bo);
                mma16816(d[j], ah01.x, ah13.x, ah01.y, ah13.y, bh.x, bh.y);
                mma16816(d[j], al01.x, al13.x, al01.y, al13.y, bh.x, bh.y);
                mma16816(d[j], ah01.x, ah13.x, ah01.y, ah13.y, bl.x, bl.y);
            }
        }
        __syncthreads();   // all L1 reads of A done before h1/x writes

        // ---------------- layer-1 elementwise -> h1 into A cols u ----------------
#pragma unroll
        for (int j = 0; j < NT; j++) {
            float e0 = __shfl_xor_sync(0xffffffffu, (q & 1) ? d[j][0] : d[j][2], 1);
            float e1 = __shfl_xor_sync(0xffffffffu, (q & 1) ? d[j][1] : d[j][3], 1);
            float gi, gf, gg, go;
            if (q & 1) { gi = e0; gf = e1; gg = d[j][2]; go = d[j][3]; }
            else       { gi = d[j][0]; gf = d[j][1]; gg = e0; go = e1; }
            float c = fmaf(sigf(gf), c1[j], sigf(gi) * tanhfast(gg));
            c1[j] = c;
            float h = sigf(go) * tanhfast(c);
            int u = 26 * wn + 2 * j + (q >> 1);        // u==51 -> dummy col, harmless
            uint16_t hi, lo; bsplit(h, hi, lo);
            uint32_t ab = OFF_A + row_e * (SA * 2);
            *(uint16_t*)(smc + ab + pcol(u) * 2) = hi;
            *(uint16_t*)(smc + ab + (128 + pcol(u)) * 2) = lo;
        }
        if (tid < MR) {    // x(t+1) store (col 52 is x0-multiplied only in L1; B2 row 52 = 0)
            uint16_t hi, lo; bsplit(xnext, hi, lo);
            uint32_t ab = OFF_A + tid * (SA * 2);
            *(uint16_t*)(smc + ab + pcol(52) * 2) = hi;
            *(uint16_t*)(smc + ab + (128 + pcol(52)) * 2) = lo;
            if (step + 2 < T_)
                xnext = __ldg(&x[(size_t)(bbase + tid) * T_ + step + 2]);
        }
        __syncthreads();   // h1(t) visible to all

        // ---------------- layer-2 MMA: gates2 = [h1 | bias | h2] ----------------
#pragma unroll
        for (int j = 0; j < NT; j++) { d[j][0] = 0.f; d[j][1] = 0.f; d[j][2] = 0.f; d[j][3] = 0.f; }
#pragma unroll
        for (int ks = 0; ks < K2S; ks++) {
            uint32_t ko = (uint32_t)(ks * 16) * 2 + aq;
            uint2 ah01 = *(const uint2*)(smc + arow0 + ko);
            uint2 ah13 = *(const uint2*)(smc + arow8 + ko);
            uint2 al01 = *(const uint2*)(smc + arow0 + ko + 256);
            uint2 al13 = *(const uint2*)(smc + arow8 + ko + 256);
#pragma unroll
            for (int j = 0; j < NT; j++) {
                uint32_t nrow = (uint32_t)(wn * 104 + 8 * j + rql);
                uint32_t bo = nrow * (SB2 * 2) + ko;
                uint2 bh = *(const uint2*)(smc + OFF_B2H + bo);
                uint2 bl = *(const uint2*)(smc + OFF_B2L + bo);
                mma16816(d[j], ah01.x, ah13.x, ah01.y, ah13.y, bh.x, bh.y);
                mma16816(d[j], al01.x, al13.x, al01.y, al13.y, bh.x, bh.y);
                mma16816(d[j], ah01.x, ah13.x, ah01.y, ah13.y, bl.x, bl.y);
            }
        }
        __syncthreads();   // all L2 reads done before h2 writes

        // ---------------- layer-2 elementwise -> h2 into A cols 56+u, y ----------------
        float yp = 0.f;
#pragma unroll
        for (int j = 0; j < NT; j++) {
            float e0 = __shfl_xor_sync(0xffffffffu, (q & 1) ? d[j][0] : d[j][2], 1);
            float e1 = __shfl_xor_sync(0xffffffffu, (q & 1) ? d[j][1] : d[j][3], 1);
            float gi, gf, gg, go;
            if (q & 1) { gi = e0; gf = e1; gg = d[j][2]; go = d[j][3]; }
            else       { gi = d[j][0]; gf = d[j][1]; gg = e0; go = e1; }
            float c = fmaf(sigf(gf), c2[j], sigf(gi) * tanhfast(gg));
            c2[j] = c;
            float h = sigf(go) * tanhfast(c);
            int u = 26 * wn + 2 * j + (q >> 1);
            yp = fmaf(h, wlinf[u], yp);                // wlin[51] = 0
            uint16_t hi, lo; bsplit(h, hi, lo);
            uint32_t ab = OFF_A + row_e * (SA * 2);
            *(uint16_t*)(smc + ab + pcol(56 + u) * 2) = hi;
            *(uint16_t*)(smc + ab + (128 + pcol(56 + u)) * 2) = lo;
        }
        yp += __shfl_xor_sync(0xffffffffu, yp, 2);     // combine units 2j / 2j+1
        if (wn == 0 && q < 2) ysm[row_e] = yp;
        __syncthreads();   // h2 + ysm visible
        if (wn == 1 && q < 2)
            out[(size_t)(bbase + row_e) * T_ + step] = yp + ysm[row_e] + blin;
    }
}

extern "C" void kernel_launch(void* const* d_in, const int* in_sizes, int n_in,
                              void* d_out, int out_size) {
    (void)in_sizes; (void)n_in; (void)out_size;
    cudaFuncSetAttribute(lstm_hmma_kernel,
                         cudaFuncAttributeMaxDynamicSharedMemorySize, SMEM_BYTES);
    lstm_hmma_kernel<<<NCTA, NTH, SMEM_BYTES>>>(
        (const float*)d_in[0], (const float*)d_in[1], (const float*)d_in[2],
        (const float*)d_in[3], (const float*)d_in[4], (const float*)d_in[5],
        (const float*)d_in[6], (const float*)d_in[7], (const float*)d_in[8],
        (const float*)d_in[9], (const float*)d_in[10], (float*)d_out);
}